// round 8
// baseline (speedup 1.0000x reference)
#include <cuda_runtime.h>
#include <cuda_bf16.h>
#include <mma.h>
#include <cstdint>
#include <cstring>

using namespace nvcuda;

#define N_USERS 100000
#define N_ITEMS 100000
#define DIM     128
#define NUM_R   4
#define N_EDGES 1000000

#define GRID_U  148
#define TM      64
#define NT      ((N_USERS + TM - 1) / TM)   // 1563

#define SCAN_N  (2 * NUM_R * N_USERS)       // 800000 count slots
#define NTILES  ((SCAN_N + 1023) / 1024)    // 782
#define TOT_E   (2 * NUM_R * N_EDGES)       // 8M csr entries

// ---------------- device scratch (static globals; no allocation) ----------------
__device__ float g_U[(size_t)N_USERS * DIM];
__device__ float g_I[(size_t)N_ITEMS * DIM];
__device__ float g_degU[NUM_R * N_USERS];
__device__ float g_degI[NUM_R * N_ITEMS];
__device__ __nv_bfloat16 g_Wb[(size_t)5 * 2 * 16384];   // Wp,Ws[0..3] x hi,lo, [n][k] bf16
__device__ int  g_cnt[SCAN_N];
__device__ int  g_cur[SCAN_N];
__device__ int  g_off[SCAN_N + 1];
__device__ int  g_tile[NTILES];
__device__ int2 g_csr[TOT_E];               // {src, val_bits}

// ---------------- count + degree (merged) ----------------
__global__ void count_kernel(const int* __restrict__ rows, const int* __restrict__ cols,
                             const float* __restrict__ vals)
{
    int idx = blockIdx.x * blockDim.x + threadIdx.x;
    if (idx >= NUM_R * N_EDGES) return;
    int r = idx / N_EDGES;
    int row = rows[idx], col = cols[idx];
    float v = vals[idx];
    atomicAdd(&g_degU[r * N_USERS + row], v);
    atomicAdd(&g_degI[r * N_ITEMS + col], v);
    atomicAdd(&g_cnt[r * N_USERS + row], 1);
    atomicAdd(&g_cnt[NUM_R * N_USERS + r * N_ITEMS + col], 1);
}

// ---------------- 3-kernel exclusive scan over g_cnt -> g_off ----------------
__global__ __launch_bounds__(256) void scan1_kernel()
{
    __shared__ int ssum[256];
    int t = threadIdx.x;
    int base = blockIdx.x * 1024 + t * 4;
    int c[4];
#pragma unroll
    for (int j = 0; j < 4; ++j) c[j] = (base + j < SCAN_N) ? g_cnt[base + j] : 0;
    int tsum = c[0] + c[1] + c[2] + c[3];
    ssum[t] = tsum;
    __syncthreads();
#pragma unroll
    for (int o = 1; o < 256; o <<= 1) {
        int v = (t >= o) ? ssum[t - o] : 0;
        __syncthreads();
        ssum[t] += v;
        __syncthreads();
    }
    int run = ssum[t] - tsum;
#pragma unroll
    for (int j = 0; j < 4; ++j) {
        if (base + j < SCAN_N) g_off[base + j] = run;
        run += c[j];
    }
    if (t == 255) g_tile[blockIdx.x] = ssum[255];
}

__global__ __launch_bounds__(1024) void scan2_kernel()
{
    __shared__ int s[1024];
    int t = threadIdx.x;
    int orig = (t < NTILES) ? g_tile[t] : 0;
    s[t] = orig;
    __syncthreads();
#pragma unroll
    for (int o = 1; o < 1024; o <<= 1) {
        int v = (t >= o) ? s[t - o] : 0;
        __syncthreads();
        s[t] += v;
        __syncthreads();
    }
    if (t < NTILES) g_tile[t] = s[t] - orig;
}

__global__ __launch_bounds__(256) void scan3_kernel()
{
    int add = g_tile[blockIdx.x];
    int base = blockIdx.x * 1024 + threadIdx.x * 4;
#pragma unroll
    for (int j = 0; j < 4; ++j)
        if (base + j < SCAN_N) g_off[base + j] += add;
    if (blockIdx.x == 0 && threadIdx.x == 0) g_off[SCAN_N] = TOT_E;
}

// ---------------- CSR fill ----------------
__global__ void fill_kernel(const int* __restrict__ rows, const int* __restrict__ cols,
                            const float* __restrict__ vals)
{
    int idx = blockIdx.x * blockDim.x + threadIdx.x;
    if (idx >= NUM_R * N_EDGES) return;
    int r = idx / N_EDGES;
    int row = rows[idx], col = cols[idx];
    int vb = __float_as_int(vals[idx]);
    int kR = r * N_USERS + row;
    int pR = g_off[kR] + atomicAdd(&g_cur[kR], 1);
    g_csr[pR] = make_int2(col, vb);
    int kC = NUM_R * N_USERS + r * N_ITEMS + col;
    int pC = g_off[kC] + atomicAdd(&g_cur[kC], 1);
    g_csr[pC] = make_int2(row, vb);
}

// ---------------- weight prep: transpose + bf16 split ----------------
__global__ __launch_bounds__(256) void wprep_kernel(const float* __restrict__ Wp,
                                                    const float* __restrict__ Ws)
{
    int w = blockIdx.x;
    const float* W = (w == 0) ? Wp : Ws + (size_t)(w - 1) * DIM * DIM;
    __nv_bfloat16* hi = g_Wb + (size_t)w * 2 * 16384;
    __nv_bfloat16* lo = hi + 16384;
    for (int e = threadIdx.x; e < DIM * DIM; e += blockDim.x) {
        int k = e >> 7, n = e & 127;
        float x = W[e];
        __nv_bfloat16 h = __float2bfloat16(x);
        __nv_bfloat16 l = __float2bfloat16(x - __bfloat162float(h));
        hi[n * DIM + k] = h;
        lo[n * DIM + k] = l;
    }
}

// ================= fused SpMM + WMMA update (persistent) =================
// X[tile,:] = X @ Wp + (inv * (A_csr @ feats))[tile,:] @ Ws
// Gather phase computes AGG rows in registers and writes bf16 hi/lo straight
// into A smem; no global AGG buffer exists.
#define LDA       136
#define ASTRIDE_B (LDA * 2)
#define SM_STAGE  0                           // 64x128 fp32 = 32768
#define SM_AH     (SM_STAGE + 32768)
#define SM_AL     (SM_AH + TM * ASTRIDE_B)
#define SM_B      (SM_AL + TM * ASTRIDE_B)
#define BMAT      (128 * ASTRIDE_B)
#define SM_BYTES  (SM_B + 4 * BMAT)           // 205824

typedef wmma::fragment<wmma::matrix_a, 16, 16, 16, __nv_bfloat16, wmma::row_major> FragA;
typedef wmma::fragment<wmma::matrix_b, 16, 16, 16, __nv_bfloat16, wmma::col_major> FragB;
typedef wmma::fragment<wmma::accumulator, 16, 16, 16, float> FragC;

__device__ __forceinline__ uint32_t smem_u32(const void* p) {
    uint32_t a;
    asm("{ .reg .u64 t; cvta.to.shared.u64 t, %1; cvt.u32.u64 %0, t; }" : "=r"(a) : "l"(p));
    return a;
}
__device__ __forceinline__ void cp_async16(uint32_t smem_dst, const void* gsrc) {
    asm volatile("cp.async.cg.shared.global [%0], [%1], 16;" :: "r"(smem_dst), "l"(gsrc));
}
#define CP_COMMIT() asm volatile("cp.async.commit_group;" ::: "memory")
#define CP_WAIT0()  asm volatile("cp.async.wait_group 0;" ::: "memory")

__device__ __forceinline__ void stage_load(const float* __restrict__ src, int bm, int M,
                                           uint32_t stageAddr, int tid)
{
#pragma unroll
    for (int i = 0; i < 8; ++i) {
        int idx = i * 256 + tid;
        int r = idx >> 5, c4 = idx & 31;
        int rowg = bm + r;
        if (rowg >= M) rowg = M - 1;
        cp_async16(stageAddr + (uint32_t)idx * 16, src + (size_t)rowg * DIM + c4 * 4);
    }
    CP_COMMIT();
}

// split fp32x4 -> hi/lo bf16x4 and store to A smem at [row][c4*4..]
__device__ __forceinline__ void split_store(float4 v, char* hi, char* lo, int row, int c4)
{
    __nv_bfloat162 h01 = __floats2bfloat162_rn(v.x, v.y);
    __nv_bfloat162 h23 = __floats2bfloat162_rn(v.z, v.w);
    __nv_bfloat162 l01 = __floats2bfloat162_rn(v.x - __bfloat162float(h01.x),
                                               v.y - __bfloat162float(h01.y));
    __nv_bfloat162 l23 = __floats2bfloat162_rn(v.z - __bfloat162float(h23.x),
                                               v.w - __bfloat162float(h23.y));
    uint32_t off = (uint32_t)row * ASTRIDE_B + (uint32_t)c4 * 8;
    uint2 hv, lv;
    memcpy(&hv.x, &h01, 4); memcpy(&hv.y, &h23, 4);
    memcpy(&lv.x, &l01, 4); memcpy(&lv.y, &l23, 4);
    *reinterpret_cast<uint2*>(hi + off) = hv;
    *reinterpret_cast<uint2*>(lo + off) = lv;
}

__device__ __forceinline__ void cvt_stage(const char* __restrict__ stage, char* hi, char* lo,
                                          int tid)
{
#pragma unroll
    for (int it = 0; it < 8; ++it) {
        int idx = it * 256 + tid;
        float4 v = *reinterpret_cast<const float4*>(stage + (size_t)idx * 16);
        split_store(v, hi, lo, idx >> 5, idx & 31);
    }
}

__device__ __forceinline__ void mma_term(const __nv_bfloat16* aStrip,
                                         const __nv_bfloat16* bStrip,
                                         FragC (&acc)[2][2])
{
#pragma unroll
    for (int ks = 0; ks < 8; ++ks) {
        FragA a[2];
        FragB b[2];
#pragma unroll
        for (int mi = 0; mi < 2; ++mi)
            wmma::load_matrix_sync(a[mi], aStrip + (size_t)(mi * 16) * LDA + ks * 16, LDA);
#pragma unroll
        for (int j = 0; j < 2; ++j)
            wmma::load_matrix_sync(b[j], bStrip + (size_t)(j * 16) * LDA + ks * 16, LDA);
#pragma unroll
        for (int mi = 0; mi < 2; ++mi)
#pragma unroll
            for (int j = 0; j < 2; ++j)
                wmma::mma_sync(acc[mi][j], a[mi], b[j], acc[mi][j]);
    }
}

__global__ __launch_bounds__(256, 1)
void update_fused_kernel(float* __restrict__ X, const float* __restrict__ feats,
                         const float* __restrict__ deg, int kbase,
                         const __nv_bfloat16* __restrict__ wp_pair,
                         const __nv_bfloat16* __restrict__ ws_pair, int M)
{
    extern __shared__ char sm[];
    const uint32_t sb = smem_u32(sm);
    const int tid = threadIdx.x;
    const int wid = tid >> 5;
    const int lane = tid & 31;
    const int mg  = wid & 1;
    const int ng  = wid >> 1;

    // ---- load all 4 B matrices to smem once ----
    {
        const float4* srcs[4] = {
            reinterpret_cast<const float4*>(wp_pair),
            reinterpret_cast<const float4*>(wp_pair + 16384),
            reinterpret_cast<const float4*>(ws_pair),
            reinterpret_cast<const float4*>(ws_pair + 16384)};
#pragma unroll
        for (int w = 0; w < 4; ++w) {
            char* dst = sm + SM_B + w * BMAT;
#pragma unroll
            for (int i = 0; i < 8; ++i) {
                int idx = i * 256 + tid;
                int row = idx >> 4, c = idx & 15;
                *reinterpret_cast<float4*>(dst + (uint32_t)row * ASTRIDE_B + c * 16) = srcs[w][idx];
            }
        }
    }

    const uint32_t stageAddr = sb + SM_STAGE;
    char* stage = sm + SM_STAGE;
    char* aHbuf = sm + SM_AH;
    char* aLbuf = sm + SM_AL;

    const __nv_bfloat16* aH = (const __nv_bfloat16*)aHbuf + (size_t)mg * 32 * LDA;
    const __nv_bfloat16* aL = (const __nv_bfloat16*)aLbuf + (size_t)mg * 32 * LDA;
    const __nv_bfloat16* bPH = (const __nv_bfloat16*)(sm + SM_B + 0 * BMAT) + (size_t)ng * 32 * LDA;
    const __nv_bfloat16* bPL = (const __nv_bfloat16*)(sm + SM_B + 1 * BMAT) + (size_t)ng * 32 * LDA;
    const __nv_bfloat16* bSH = (const __nv_bfloat16*)(sm + SM_B + 2 * BMAT) + (size_t)ng * 32 * LDA;
    const __nv_bfloat16* bSL = (const __nv_bfloat16*)(sm + SM_B + 3 * BMAT) + (size_t)ng * 32 * LDA;

    const float4* f4 = reinterpret_cast<const float4*>(feats);

    stage_load(X, (int)blockIdx.x * TM, M, stageAddr, tid);

    for (int t = blockIdx.x; t < NT; t += GRID_U) {
        const int bm = t * TM;

        FragC acc[2][2];
#pragma unroll
        for (int mi = 0; mi < 2; ++mi)
#pragma unroll
            for (int j = 0; j < 2; ++j) wmma::fill_fragment(acc[mi][j], 0.0f);

        __syncthreads();   // prev-iter MMA done reading A bufs

        // ===== gather phase: AGG rows for this tile -> A bufs (scaled, bf16 split) =====
        // warp w handles tile rows [w*8, w*8+8)
#pragma unroll 1
        for (int rr = 0; rr < 8; ++rr) {
            int row = wid * 8 + rr;
            int d = bm + row;
            if (d >= M) d = M - 1;
            int e0 = __ldg(&g_off[kbase + d]);
            int e1 = __ldg(&g_off[kbase + d + 1]);
            float4 a0 = make_float4(0.f, 0.f, 0.f, 0.f);
            float4 a1 = make_float4(0.f, 0.f, 0.f, 0.f);
            float4 a2 = make_float4(0.f, 0.f, 0.f, 0.f);
            float4 a3 = make_float4(0.f, 0.f, 0.f, 0.f);
            int e = e0;
            for (; e + 3 < e1; e += 4) {
                int2 p0 = __ldg(&g_csr[e]);
                int2 p1 = __ldg(&g_csr[e + 1]);
                int2 p2 = __ldg(&g_csr[e + 2]);
                int2 p3 = __ldg(&g_csr[e + 3]);
                float4 x0 = __ldg(&f4[(size_t)p0.x * 32 + lane]);
                float4 x1 = __ldg(&f4[(size_t)p1.x * 32 + lane]);
                float4 x2 = __ldg(&f4[(size_t)p2.x * 32 + lane]);
                float4 x3 = __ldg(&f4[(size_t)p3.x * 32 + lane]);
                float v0 = __int_as_float(p0.y), v1 = __int_as_float(p1.y);
                float v2 = __int_as_float(p2.y), v3 = __int_as_float(p3.y);
                a0.x = fmaf(v0, x0.x, a0.x); a0.y = fmaf(v0, x0.y, a0.y);
                a0.z = fmaf(v0, x0.z, a0.z); a0.w = fmaf(v0, x0.w, a0.w);
                a1.x = fmaf(v1, x1.x, a1.x); a1.y = fmaf(v1, x1.y, a1.y);
                a1.z = fmaf(v1, x1.z, a1.z); a1.w = fmaf(v1, x1.w, a1.w);
                a2.x = fmaf(v2, x2.x, a2.x); a2.y = fmaf(v2, x2.y, a2.y);
                a2.z = fmaf(v2, x2.z, a2.z); a2.w = fmaf(v2, x2.w, a2.w);
                a3.x = fmaf(v3, x3.x, a3.x); a3.y = fmaf(v3, x3.y, a3.y);
                a3.z = fmaf(v3, x3.z, a3.z); a3.w = fmaf(v3, x3.w, a3.w);
            }
            for (; e < e1; ++e) {
                int2 p = __ldg(&g_csr[e]);
                float v = __int_as_float(p.y);
                float4 x = __ldg(&f4[(size_t)p.x * 32 + lane]);
                a0.x = fmaf(v, x.x, a0.x); a0.y = fmaf(v, x.y, a0.y);
                a0.z = fmaf(v, x.z, a0.z); a0.w = fmaf(v, x.w, a0.w);
            }
            a0.x += a1.x + a2.x + a3.x;
            a0.y += a1.y + a2.y + a3.y;
            a0.z += a1.z + a2.z + a3.z;
            a0.w += a1.w + a2.w + a3.w;
            float s = 1.0f / (__ldg(&deg[d]) + 1.0f);
            a0.x *= s; a0.y *= s; a0.z *= s; a0.w *= s;
            split_store(a0, aHbuf, aLbuf, row, lane);
        }
        __syncthreads();

        // ===== MMA: (inv*AGG) @ Ws =====
        mma_term(aH, bSH, acc);
        mma_term(aH, bSL, acc);
        mma_term(aL, bSH, acc);
        __syncthreads();   // done reading A bufs

        // ===== X phase: cvt staged X, then MMA X @ Wp =====
        CP_WAIT0();
        cvt_stage(stage, aHbuf, aLbuf, tid);
        __syncthreads();
        if (t + GRID_U < NT)
            stage_load(X, (t + GRID_U) * TM, M, stageAddr, tid);
        mma_term(aH, bPH, acc);
        mma_term(aH, bPL, acc);
        mma_term(aL, bPH, acc);

        // ===== epilogue: direct global store =====
#pragma unroll
        for (int mi = 0; mi < 2; ++mi) {
            int row0 = bm + mg * 32 + mi * 16;
            if (row0 < M) {
#pragma unroll
                for (int j = 0; j < 2; ++j)
                    wmma::store_matrix_sync(X + (size_t)row0 * DIM + ng * 32 + j * 16,
                                            acc[mi][j], DIM, wmma::mem_row_major);
            }
        }
    }
}

// ---------------- final leaky-relu + write out [U ; I] ----------------
__global__ void finalize_kernel(float* __restrict__ out)
{
    const size_t half4  = (size_t)N_USERS * DIM / 4;
    const size_t total4 = 2 * half4;
    size_t idx = (size_t)blockIdx.x * blockDim.x + threadIdx.x;
    if (idx >= total4) return;
    float4 v = (idx < half4) ? reinterpret_cast<const float4*>(g_U)[idx]
                             : reinterpret_cast<const float4*>(g_I)[idx - half4];
    v.x = v.x > 0.f ? v.x : 0.01f * v.x;
    v.y = v.y > 0.f ? v.y : 0.01f * v.y;
    v.z = v.z > 0.f ? v.z : 0.01f * v.z;
    v.w = v.w > 0.f ? v.w : 0.01f * v.w;
    reinterpret_cast<float4*>(out)[idx] = v;
}

// ---------------- launch ----------------
extern "C" void kernel_launch(void* const* d_in, const int* in_sizes, int n_in,
                              void* d_out, int out_size)
{
    const float* u_emb = (const float*)d_in[0];
    const float* i_emb = (const float*)d_in[1];
    const float* Wp    = (const float*)d_in[2];
    const float* Ws    = (const float*)d_in[3];
    const float* vals  = (const float*)d_in[4];
    const int*   rows  = (const int*)d_in[5];
    const int*   cols  = (const int*)d_in[6];
    float*       out   = (float*)d_out;

    void *pU, *pI, *pDU, *pDI, *pWb, *pCnt, *pCur;
    cudaGetSymbolAddress(&pU,  g_U);
    cudaGetSymbolAddress(&pI,  g_I);
    cudaGetSymbolAddress(&pDU, g_degU);
    cudaGetSymbolAddress(&pDI, g_degI);
    cudaGetSymbolAddress(&pWb, g_Wb);
    cudaGetSymbolAddress(&pCnt, g_cnt);
    cudaGetSymbolAddress(&pCur, g_cur);

    cudaFuncSetAttribute(update_fused_kernel, cudaFuncAttributeMaxDynamicSharedMemorySize, SM_BYTES);

    const size_t embBytes = (size_t)N_USERS * DIM * sizeof(float);
    cudaMemcpyAsync(pU, u_emb, embBytes, cudaMemcpyDeviceToDevice, 0);
    cudaMemcpyAsync(pI, i_emb, embBytes, cudaMemcpyDeviceToDevice, 0);
    cudaMemsetAsync(pDU, 0, sizeof(float) * NUM_R * N_USERS, 0);
    cudaMemsetAsync(pDI, 0, sizeof(float) * NUM_R * N_ITEMS, 0);
    cudaMemsetAsync(pCnt, 0, sizeof(int) * SCAN_N, 0);
    cudaMemsetAsync(pCur, 0, sizeof(int) * SCAN_N, 0);

    wprep_kernel<<<5, 256>>>(Wp, Ws);
    count_kernel<<<(NUM_R * N_EDGES + 255) / 256, 256>>>(rows, cols, vals);
    scan1_kernel<<<NTILES, 256>>>();
    scan2_kernel<<<1, 1024>>>();
    scan3_kernel<<<NTILES, 256>>>();
    fill_kernel<<<(NUM_R * N_EDGES + 255) / 256, 256>>>(rows, cols, vals);

    const __nv_bfloat16* wb = (const __nv_bfloat16*)pWb;

    for (int r = 0; r < NUM_R; ++r) {
        const __nv_bfloat16* wp_pair = wb;
        const __nv_bfloat16* ws_pair = wb + (size_t)(1 + r) * 2 * 16384;

        // ---- u update: gathers from I via CSR segment r ----
        update_fused_kernel<<<GRID_U, 256, SM_BYTES>>>(
            (float*)pU, (const float*)pI, (const float*)pDU + (size_t)r * N_USERS,
            r * N_USERS, wp_pair, ws_pair, N_USERS);

        // ---- i update: gathers from updated U via CSR segment NUM_R + r ----
        update_fused_kernel<<<GRID_U, 256, SM_BYTES>>>(
            (float*)pI, (const float*)pU, (const float*)pDI + (size_t)r * N_ITEMS,
            (NUM_R + r) * N_ITEMS, wp_pair, ws_pair, N_ITEMS);
    }

    const size_t total4 = 2 * ((size_t)N_USERS * DIM / 4);
    finalize_kernel<<<(unsigned)((total4 + 255) / 256), 256>>>(out);
}

// round 9
// speedup vs baseline: 1.9068x; 1.9068x over previous
#include <cuda_runtime.h>
#include <cuda_bf16.h>
#include <mma.h>
#include <cstdint>
#include <cstring>

using namespace nvcuda;

#define N_USERS 100000
#define N_ITEMS 100000
#define DIM     128
#define NUM_R   4
#define N_EDGES 1000000

#define GRID_U  148
#define TM      64
#define NT      ((N_USERS + TM - 1) / TM)   // 1563

#define SCAN_N  (2 * NUM_R * N_USERS)
#define NTILES  ((SCAN_N + 1023) / 1024)
#define TOT_E   (2 * NUM_R * N_EDGES)

// ---------------- device scratch ----------------
__device__ float g_U[(size_t)N_USERS * DIM];
__device__ float g_I[(size_t)N_ITEMS * DIM];
__device__ __nv_bfloat16 g_Uh[(size_t)N_USERS * DIM];
__device__ __nv_bfloat16 g_Ul[(size_t)N_USERS * DIM];
__device__ __nv_bfloat16 g_Ih[(size_t)N_ITEMS * DIM];
__device__ __nv_bfloat16 g_Il[(size_t)N_ITEMS * DIM];
__device__ __nv_bfloat16 g_Gh[(size_t)N_USERS * DIM];   // scaled AGG split
__device__ __nv_bfloat16 g_Gl[(size_t)N_USERS * DIM];
__device__ float g_degU[NUM_R * N_USERS];
__device__ float g_degI[NUM_R * N_ITEMS];
__device__ __nv_bfloat16 g_Wb[(size_t)5 * 2 * 16384];
__device__ int  g_cnt[SCAN_N];
__device__ int  g_cur[SCAN_N];
__device__ int  g_off[SCAN_N + 1];
__device__ int  g_tile[NTILES];
__device__ int2 g_csr[TOT_E];

// ---------------- split helper ----------------
__device__ __forceinline__ void split4(float4 v, uint2& hv, uint2& lv)
{
    __nv_bfloat162 h01 = __floats2bfloat162_rn(v.x, v.y);
    __nv_bfloat162 h23 = __floats2bfloat162_rn(v.z, v.w);
    __nv_bfloat162 l01 = __floats2bfloat162_rn(v.x - __bfloat162float(h01.x),
                                               v.y - __bfloat162float(h01.y));
    __nv_bfloat162 l23 = __floats2bfloat162_rn(v.z - __bfloat162float(h23.x),
                                               v.w - __bfloat162float(h23.y));
    memcpy(&hv.x, &h01, 4); memcpy(&hv.y, &h23, 4);
    memcpy(&lv.x, &l01, 4); memcpy(&lv.y, &l23, 4);
}

// ---------------- init: copy emb -> fp32 + split ----------------
__global__ void init_kernel(const float* __restrict__ u_emb, const float* __restrict__ i_emb)
{
    int idx = blockIdx.x * blockDim.x + threadIdx.x;   // float4 units, 2 matrices
    const int per = N_USERS * 32;
    if (idx >= 2 * per) return;
    bool isU = idx < per;
    int j = isU ? idx : idx - per;
    float4 v = reinterpret_cast<const float4*>(isU ? u_emb : i_emb)[j];
    reinterpret_cast<float4*>(isU ? g_U : g_I)[j] = v;
    uint2 hv, lv;
    split4(v, hv, lv);
    reinterpret_cast<uint2*>(isU ? g_Uh : g_Ih)[j] = hv;
    reinterpret_cast<uint2*>(isU ? g_Ul : g_Il)[j] = lv;
}

// ---------------- count + degree ----------------
__global__ void count_kernel(const int* __restrict__ rows, const int* __restrict__ cols,
                             const float* __restrict__ vals)
{
    int idx = blockIdx.x * blockDim.x + threadIdx.x;
    if (idx >= NUM_R * N_EDGES) return;
    int r = idx / N_EDGES;
    int row = rows[idx], col = cols[idx];
    float v = vals[idx];
    atomicAdd(&g_degU[r * N_USERS + row], v);
    atomicAdd(&g_degI[r * N_ITEMS + col], v);
    atomicAdd(&g_cnt[r * N_USERS + row], 1);
    atomicAdd(&g_cnt[NUM_R * N_USERS + r * N_ITEMS + col], 1);
}

// ---------------- scans ----------------
__global__ __launch_bounds__(256) void scan1_kernel()
{
    __shared__ int ssum[256];
    int t = threadIdx.x;
    int base = blockIdx.x * 1024 + t * 4;
    int c[4];
#pragma unroll
    for (int j = 0; j < 4; ++j) c[j] = (base + j < SCAN_N) ? g_cnt[base + j] : 0;
    int tsum = c[0] + c[1] + c[2] + c[3];
    ssum[t] = tsum;
    __syncthreads();
#pragma unroll
    for (int o = 1; o < 256; o <<= 1) {
        int v = (t >= o) ? ssum[t - o] : 0;
        __syncthreads();
        ssum[t] += v;
        __syncthreads();
    }
    int run = ssum[t] - tsum;
#pragma unroll
    for (int j = 0; j < 4; ++j) {
        if (base + j < SCAN_N) g_off[base + j] = run;
        run += c[j];
    }
    if (t == 255) g_tile[blockIdx.x] = ssum[255];
}

__global__ __launch_bounds__(1024) void scan2_kernel()
{
    __shared__ int s[1024];
    int t = threadIdx.x;
    int orig = (t < NTILES) ? g_tile[t] : 0;
    s[t] = orig;
    __syncthreads();
#pragma unroll
    for (int o = 1; o < 1024; o <<= 1) {
        int v = (t >= o) ? s[t - o] : 0;
        __syncthreads();
        s[t] += v;
        __syncthreads();
    }
    if (t < NTILES) g_tile[t] = s[t] - orig;
}

__global__ __launch_bounds__(256) void scan3_kernel()
{
    int add = g_tile[blockIdx.x];
    int base = blockIdx.x * 1024 + threadIdx.x * 4;
#pragma unroll
    for (int j = 0; j < 4; ++j)
        if (base + j < SCAN_N) g_off[base + j] += add;
    if (blockIdx.x == 0 && threadIdx.x == 0) g_off[SCAN_N] = TOT_E;
}

// ---------------- CSR fill ----------------
__global__ void fill_kernel(const int* __restrict__ rows, const int* __restrict__ cols,
                            const float* __restrict__ vals)
{
    int idx = blockIdx.x * blockDim.x + threadIdx.x;
    if (idx >= NUM_R * N_EDGES) return;
    int r = idx / N_EDGES;
    int row = rows[idx], col = cols[idx];
    int vb = __float_as_int(vals[idx]);
    int kR = r * N_USERS + row;
    int pR = g_off[kR] + atomicAdd(&g_cur[kR], 1);
    g_csr[pR] = make_int2(col, vb);
    int kC = NUM_R * N_USERS + r * N_ITEMS + col;
    int pC = g_off[kC] + atomicAdd(&g_cur[kC], 1);
    g_csr[pC] = make_int2(row, vb);
}

// ---------------- CSR SpMM: warp per dst row -> scaled bf16 split AGG ----------------
__global__ __launch_bounds__(256) void spmm_csr_kernel(const float* __restrict__ feats,
                                                       const float* __restrict__ deg,
                                                       int kbase)
{
    int gw = (blockIdx.x * blockDim.x + threadIdx.x) >> 5;
    int lane = threadIdx.x & 31;
    if (gw >= N_USERS) return;
    int e0 = g_off[kbase + gw];
    int e1 = g_off[kbase + gw + 1];
    float4 acc0 = make_float4(0.f, 0.f, 0.f, 0.f);
    float4 acc1 = make_float4(0.f, 0.f, 0.f, 0.f);
    int e = e0;
    for (; e + 1 < e1; e += 2) {
        int2 p0 = __ldg(&g_csr[e]);
        int2 p1 = __ldg(&g_csr[e + 1]);
        float v0 = __int_as_float(p0.y), v1 = __int_as_float(p1.y);
        float4 x0 = __ldg(&reinterpret_cast<const float4*>(feats + (size_t)p0.x * DIM)[lane]);
        float4 x1 = __ldg(&reinterpret_cast<const float4*>(feats + (size_t)p1.x * DIM)[lane]);
        acc0.x = fmaf(v0, x0.x, acc0.x); acc0.y = fmaf(v0, x0.y, acc0.y);
        acc0.z = fmaf(v0, x0.z, acc0.z); acc0.w = fmaf(v0, x0.w, acc0.w);
        acc1.x = fmaf(v1, x1.x, acc1.x); acc1.y = fmaf(v1, x1.y, acc1.y);
        acc1.z = fmaf(v1, x1.z, acc1.z); acc1.w = fmaf(v1, x1.w, acc1.w);
    }
    if (e < e1) {
        int2 p = __ldg(&g_csr[e]);
        float v = __int_as_float(p.y);
        float4 x = __ldg(&reinterpret_cast<const float4*>(feats + (size_t)p.x * DIM)[lane]);
        acc0.x = fmaf(v, x.x, acc0.x); acc0.y = fmaf(v, x.y, acc0.y);
        acc0.z = fmaf(v, x.z, acc0.z); acc0.w = fmaf(v, x.w, acc0.w);
    }
    float s = 1.0f / (__ldg(&deg[gw]) + 1.0f);
    acc0.x = (acc0.x + acc1.x) * s; acc0.y = (acc0.y + acc1.y) * s;
    acc0.z = (acc0.z + acc1.z) * s; acc0.w = (acc0.w + acc1.w) * s;
    uint2 hv, lv;
    split4(acc0, hv, lv);
    reinterpret_cast<uint2*>(g_Gh)[(size_t)gw * 32 + lane] = hv;
    reinterpret_cast<uint2*>(g_Gl)[(size_t)gw * 32 + lane] = lv;
}

// ---------------- weight prep ----------------
__global__ __launch_bounds__(256) void wprep_kernel(const float* __restrict__ Wp,
                                                    const float* __restrict__ Ws)
{
    int w = blockIdx.x;
    const float* W = (w == 0) ? Wp : Ws + (size_t)(w - 1) * DIM * DIM;
    __nv_bfloat16* hi = g_Wb + (size_t)w * 2 * 16384;
    __nv_bfloat16* lo = hi + 16384;
    for (int e = threadIdx.x; e < DIM * DIM; e += blockDim.x) {
        int k = e >> 7, n = e & 127;
        float x = W[e];
        __nv_bfloat16 h = __float2bfloat16(x);
        __nv_bfloat16 l = __float2bfloat16(x - __bfloat162float(h));
        hi[n * DIM + k] = h;
        lo[n * DIM + k] = l;
    }
}

// ================= pipelined WMMA update (no conversion, split operands) =========
#define LDA       136
#define ASTRIDE_B (LDA * 2)
#define ABUF      (TM * ASTRIDE_B)            // 17408
#define SM_A      0                           // set0 hi, set0 lo, set1 hi, set1 lo
#define SM_B      (4 * ABUF)                  // 69632
#define BMAT      (128 * ASTRIDE_B)
#define SM_BYTES  (SM_B + 4 * BMAT)           // 208896

typedef wmma::fragment<wmma::matrix_a, 16, 16, 16, __nv_bfloat16, wmma::row_major> FragA;
typedef wmma::fragment<wmma::matrix_b, 16, 16, 16, __nv_bfloat16, wmma::col_major> FragB;
typedef wmma::fragment<wmma::accumulator, 16, 16, 16, float> FragC;

__device__ __forceinline__ uint32_t smem_u32(const void* p) {
    uint32_t a;
    asm("{ .reg .u64 t; cvta.to.shared.u64 t, %1; cvt.u32.u64 %0, t; }" : "=r"(a) : "l"(p));
    return a;
}
__device__ __forceinline__ void cp_async16(uint32_t smem_dst, const void* gsrc) {
    asm volatile("cp.async.cg.shared.global [%0], [%1], 16;" :: "r"(smem_dst), "l"(gsrc));
}
#define CP_COMMIT() asm volatile("cp.async.commit_group;" ::: "memory")
#define CP_WAIT1()  asm volatile("cp.async.wait_group 1;" ::: "memory")

// cp.async one split tile (hi+lo) into a buffer set; commits a group.
__device__ __forceinline__ void load_split_tile(const __nv_bfloat16* __restrict__ Hs,
                                                const __nv_bfloat16* __restrict__ Ls,
                                                int bm, int M,
                                                uint32_t dstH, uint32_t dstL, int tid)
{
#pragma unroll
    for (int i = 0; i < 4; ++i) {
        int idx = i * 256 + tid;            // 1024 16B chunks per buf
        int row = idx >> 4, c = idx & 15;
        int rowg = bm + row;
        if (rowg >= M) rowg = M - 1;
        uint32_t dof = (uint32_t)row * ASTRIDE_B + (uint32_t)c * 16;
        size_t sof = (size_t)rowg * 256 + (size_t)c * 16;
        cp_async16(dstH + dof, (const char*)Hs + sof);
        cp_async16(dstL + dof, (const char*)Ls + sof);
    }
    CP_COMMIT();
}

__device__ __forceinline__ void mma_term(const __nv_bfloat16* aStrip,
                                         const __nv_bfloat16* bStrip,
                                         FragC (&acc)[2][2])
{
#pragma unroll
    for (int ks = 0; ks < 8; ++ks) {
        FragA a[2];
        FragB b[2];
#pragma unroll
        for (int mi = 0; mi < 2; ++mi)
            wmma::load_matrix_sync(a[mi], aStrip + (size_t)(mi * 16) * LDA + ks * 16, LDA);
#pragma unroll
        for (int j = 0; j < 2; ++j)
            wmma::load_matrix_sync(b[j], bStrip + (size_t)(j * 16) * LDA + ks * 16, LDA);
#pragma unroll
        for (int mi = 0; mi < 2; ++mi)
#pragma unroll
            for (int j = 0; j < 2; ++j)
                wmma::mma_sync(acc[mi][j], a[mi], b[j], acc[mi][j]);
    }
}

__global__ __launch_bounds__(256, 1)
void update_mma_kernel(float* __restrict__ Xf,
                       __nv_bfloat16* __restrict__ Xh, __nv_bfloat16* __restrict__ Xl,
                       const __nv_bfloat16* __restrict__ wp_pair,
                       const __nv_bfloat16* __restrict__ ws_pair, int M)
{
    extern __shared__ char sm[];
    const uint32_t sb = smem_u32(sm);
    const int tid = threadIdx.x;
    const int wid = tid >> 5;
    const int mg  = wid & 1;
    const int ng  = wid >> 1;

    // ---- B matrices via cp.async (overlaps with first tile loads) ----
    {
        const __nv_bfloat16* srcs[4] = {wp_pair, wp_pair + 16384, ws_pair, ws_pair + 16384};
#pragma unroll
        for (int w = 0; w < 4; ++w) {
            uint32_t dst = sb + SM_B + w * BMAT;
#pragma unroll
            for (int i = 0; i < 8; ++i) {
                int idx = i * 256 + tid;            // 2048 chunks
                int row = idx >> 4, c = idx & 15;
                cp_async16(dst + (uint32_t)row * ASTRIDE_B + c * 16,
                           (const char*)srcs[w] + (size_t)row * 256 + c * 16);
            }
        }
        CP_COMMIT();   // group: B
    }

    const uint32_t g0H = sb + SM_A + 0 * ABUF, g0L = sb + SM_A + 1 * ABUF;  // set0: AGG
    const uint32_t x1H = sb + SM_A + 2 * ABUF, x1L = sb + SM_A + 3 * ABUF;  // set1: X

    const __nv_bfloat16* aGH = (const __nv_bfloat16*)(sm + 0 * ABUF) + (size_t)mg * 32 * LDA;
    const __nv_bfloat16* aGL = (const __nv_bfloat16*)(sm + 1 * ABUF) + (size_t)mg * 32 * LDA;
    const __nv_bfloat16* aXH = (const __nv_bfloat16*)(sm + 2 * ABUF) + (size_t)mg * 32 * LDA;
    const __nv_bfloat16* aXL = (const __nv_bfloat16*)(sm + 3 * ABUF) + (size_t)mg * 32 * LDA;
    const __nv_bfloat16* bPH = (const __nv_bfloat16*)(sm + SM_B + 0 * BMAT) + (size_t)ng * 32 * LDA;
    const __nv_bfloat16* bPL = (const __nv_bfloat16*)(sm + SM_B + 1 * BMAT) + (size_t)ng * 32 * LDA;
    const __nv_bfloat16* bSH = (const __nv_bfloat16*)(sm + SM_B + 2 * BMAT) + (size_t)ng * 32 * LDA;
    const __nv_bfloat16* bSL = (const __nv_bfloat16*)(sm + SM_B + 3 * BMAT) + (size_t)ng * 32 * LDA;

    // prologue loads for tile 0
    {
        int bm0 = (int)blockIdx.x * TM;
        load_split_tile(g_Gh, g_Gl, bm0, M, g0H, g0L, tid);   // group: G(t0)
        load_split_tile(Xh,   Xl,   bm0, M, x1H, x1L, tid);   // group: X(t0)
    }

    for (int t = blockIdx.x; t < NT; t += GRID_U) {
        const int bm = t * TM;
        const int tn = t + GRID_U;

        FragC acc[2][2];
#pragma unroll
        for (int mi = 0; mi < 2; ++mi)
#pragma unroll
            for (int j = 0; j < 2; ++j) wmma::fill_fragment(acc[mi][j], 0.0f);

        // ===== phase G: (inv*AGG) @ Ws =====
        CP_WAIT1();            // B + G(t) landed (X(t) may be in flight)
        __syncthreads();
        mma_term(aGH, bSH, acc);
        mma_term(aGH, bSL, acc);
        mma_term(aGL, bSH, acc);
        __syncthreads();       // set0 free
        if (tn < NT) load_split_tile(g_Gh, g_Gl, tn * TM, M, g0H, g0L, tid);
        else         CP_COMMIT();

        // ===== phase X: X @ Wp =====
        CP_WAIT1();            // X(t) landed (G(t+1) may be in flight)
        __syncthreads();
        mma_term(aXH, bPH, acc);
        mma_term(aXH, bPL, acc);
        mma_term(aXL, bPH, acc);
        __syncthreads();       // set1 free -> reuse as fp32 stage

        // ===== epilogue: stage fp32 in set1, write fp32 + split =====
        float* stag = (float*)(sm + 2 * ABUF);   // 32KB fits in set1 (34.8KB)
#pragma unroll
        for (int mi = 0; mi < 2; ++mi)
#pragma unroll
            for (int j = 0; j < 2; ++j)
                wmma::store_matrix_sync(stag + (size_t)(mg * 32 + mi * 16) * 128 + ng * 32 + j * 16,
                                        acc[mi][j], 128, wmma::mem_row_major);
        __syncthreads();
#pragma unroll
        for (int i = 0; i < 8; ++i) {
            int idx = i * 256 + tid;
            int r = idx >> 5, c4 = idx & 31;
            int rowg = bm + r;
            if (rowg < M) {
                float4 v = *reinterpret_cast<const float4*>(&stag[(size_t)idx * 4]);
                *reinterpret_cast<float4*>(Xf + (size_t)rowg * DIM + c4 * 4) = v;
                uint2 hv, lv;
                split4(v, hv, lv);
                reinterpret_cast<uint2*>(Xh)[(size_t)rowg * 32 + c4] = hv;
                reinterpret_cast<uint2*>(Xl)[(size_t)rowg * 32 + c4] = lv;
            }
        }
        __syncthreads();       // stage consumed -> set1 reusable for loads
        if (tn < NT) load_split_tile(Xh, Xl, tn * TM, M, x1H, x1L, tid);
        else         CP_COMMIT();
    }
}

// ---------------- final leaky-relu + write out [U ; I] ----------------
__global__ void finalize_kernel(float* __restrict__ out)
{
    const size_t half4  = (size_t)N_USERS * DIM / 4;
    const size_t total4 = 2 * half4;
    size_t idx = (size_t)blockIdx.x * blockDim.x + threadIdx.x;
    if (idx >= total4) return;
    float4 v = (idx < half4) ? reinterpret_cast<const float4*>(g_U)[idx]
                             : reinterpret_cast<const float4*>(g_I)[idx - half4];
    v.x = v.x > 0.f ? v.x : 0.01f * v.x;
    v.y = v.y > 0.f ? v.y : 0.01f * v.y;
    v.z = v.z > 0.f ? v.z : 0.01f * v.z;
    v.w = v.w > 0.f ? v.w : 0.01f * v.w;
    reinterpret_cast<float4*>(out)[idx] = v;
}

// ---------------- launch ----------------
extern "C" void kernel_launch(void* const* d_in, const int* in_sizes, int n_in,
                              void* d_out, int out_size)
{
    const float* u_emb = (const float*)d_in[0];
    const float* i_emb = (const float*)d_in[1];
    const float* Wp    = (const float*)d_in[2];
    const float* Ws    = (const float*)d_in[3];
    const float* vals  = (const float*)d_in[4];
    const int*   rows  = (const int*)d_in[5];
    const int*   cols  = (const int*)d_in[6];
    float*       out   = (float*)d_out;

    void *pU, *pI, *pUh, *pUl, *pIh, *pIl, *pDU, *pDI, *pWb, *pCnt, *pCur;
    cudaGetSymbolAddress(&pU,  g_U);
    cudaGetSymbolAddress(&pI,  g_I);
    cudaGetSymbolAddress(&pUh, g_Uh);
    cudaGetSymbolAddress(&pUl, g_Ul);
    cudaGetSymbolAddress(&pIh, g_Ih);
    cudaGetSymbolAddress(&pIl, g_Il);
    cudaGetSymbolAddress(&pDU, g_degU);
    cudaGetSymbolAddress(&pDI, g_degI);
    cudaGetSymbolAddress(&pWb, g_Wb);
    cudaGetSymbolAddress(&pCnt, g_cnt);
    cudaGetSymbolAddress(&pCur, g_cur);

    cudaFuncSetAttribute(update_mma_kernel, cudaFuncAttributeMaxDynamicSharedMemorySize, SM_BYTES);

    cudaMemsetAsync(pDU, 0, sizeof(float) * NUM_R * N_USERS, 0);
    cudaMemsetAsync(pDI, 0, sizeof(float) * NUM_R * N_ITEMS, 0);
    cudaMemsetAsync(pCnt, 0, sizeof(int) * SCAN_N, 0);
    cudaMemsetAsync(pCur, 0, sizeof(int) * SCAN_N, 0);

    init_kernel<<<(2 * N_USERS * 32 + 255) / 256, 256>>>(u_emb, i_emb);
    wprep_kernel<<<5, 256>>>(Wp, Ws);
    count_kernel<<<(NUM_R * N_EDGES + 255) / 256, 256>>>(rows, cols, vals);
    scan1_kernel<<<NTILES, 256>>>();
    scan2_kernel<<<1, 1024>>>();
    scan3_kernel<<<NTILES, 256>>>();
    fill_kernel<<<(NUM_R * N_EDGES + 255) / 256, 256>>>(rows, cols, vals);

    const int spmm_blocks = (N_USERS * 32 + 255) / 256;
    const __nv_bfloat16* wb = (const __nv_bfloat16*)pWb;

    for (int r = 0; r < NUM_R; ++r) {
        const __nv_bfloat16* wp_pair = wb;
        const __nv_bfloat16* ws_pair = wb + (size_t)(1 + r) * 2 * 16384;

        // ---- u update: gather from I (CSR seg r), scale by degU[r] ----
        spmm_csr_kernel<<<spmm_blocks, 256>>>((const float*)pI,
                                              (const float*)pDU + (size_t)r * N_USERS,
                                              r * N_USERS);
        update_mma_kernel<<<GRID_U, 256, SM_BYTES>>>(
            (float*)pU, (__nv_bfloat16*)pUh, (__nv_bfloat16*)pUl, wp_pair, ws_pair, N_USERS);

        // ---- i update: gather from updated U (CSR seg NUM_R+r), scale by degI[r] ----
        spmm_csr_kernel<<<spmm_blocks, 256>>>((const float*)pU,
                                              (const float*)pDI + (size_t)r * N_ITEMS,
                                              (NUM_R + r) * N_ITEMS);
        update_mma_kernel<<<GRID_U, 256, SM_BYTES>>>(
            (float*)pI, (__nv_bfloat16*)pIh, (__nv_bfloat16*)pIl, wp_pair, ws_pair, N_ITEMS);
    }

    const size_t total4 = 2 * ((size_t)N_USERS * DIM / 4);
    finalize_kernel<<<(unsigned)((total4 + 255) / 256), 256>>>(out);
}

// round 10
// speedup vs baseline: 1.9625x; 1.0292x over previous
#include <cuda_runtime.h>
#include <cuda_bf16.h>
#include <mma.h>
#include <cstdint>
#include <cstring>

using namespace nvcuda;

#define N_USERS 100000
#define N_ITEMS 100000
#define DIM     128
#define NUM_R   4
#define N_EDGES 1000000

#define GRID_U  148
#define TM      64
#define NTH     512
#define NT      ((N_USERS + TM - 1) / TM)   // 1563

#define SCAN_N  (2 * NUM_R * N_USERS)
#define NTILES  ((SCAN_N + 1023) / 1024)
#define TOT_E   (2 * NUM_R * N_EDGES)

// ---------------- device scratch ----------------
__device__ float g_U[(size_t)N_USERS * DIM];
__device__ float g_I[(size_t)N_ITEMS * DIM];
__device__ float g_AGG[(size_t)N_USERS * DIM];
__device__ float g_degU[NUM_R * N_USERS];
__device__ float g_degI[NUM_R * N_ITEMS];
__device__ __nv_bfloat16 g_Wb[(size_t)5 * 2 * 16384];
__device__ int  g_cnt[SCAN_N];
__device__ int  g_cur[SCAN_N];
__device__ int  g_off[SCAN_N + 1];
__device__ int  g_tile[NTILES];
__device__ int2 g_csr[TOT_E];

// ---------------- count + degree ----------------
__global__ void count_kernel(const int* __restrict__ rows, const int* __restrict__ cols,
                             const float* __restrict__ vals)
{
    int idx = blockIdx.x * blockDim.x + threadIdx.x;
    if (idx >= NUM_R * N_EDGES) return;
    int r = idx / N_EDGES;
    int row = rows[idx], col = cols[idx];
    float v = vals[idx];
    atomicAdd(&g_degU[r * N_USERS + row], v);
    atomicAdd(&g_degI[r * N_ITEMS + col], v);
    atomicAdd(&g_cnt[r * N_USERS + row], 1);
    atomicAdd(&g_cnt[NUM_R * N_USERS + r * N_ITEMS + col], 1);
}

// ---------------- scans ----------------
__global__ __launch_bounds__(256) void scan1_kernel()
{
    __shared__ int ssum[256];
    int t = threadIdx.x;
    int base = blockIdx.x * 1024 + t * 4;
    int c[4];
#pragma unroll
    for (int j = 0; j < 4; ++j) c[j] = (base + j < SCAN_N) ? g_cnt[base + j] : 0;
    int tsum = c[0] + c[1] + c[2] + c[3];
    ssum[t] = tsum;
    __syncthreads();
#pragma unroll
    for (int o = 1; o < 256; o <<= 1) {
        int v = (t >= o) ? ssum[t - o] : 0;
        __syncthreads();
        ssum[t] += v;
        __syncthreads();
    }
    int run = ssum[t] - tsum;
#pragma unroll
    for (int j = 0; j < 4; ++j) {
        if (base + j < SCAN_N) g_off[base + j] = run;
        run += c[j];
    }
    if (t == 255) g_tile[blockIdx.x] = ssum[255];
}

__global__ __launch_bounds__(1024) void scan2_kernel()
{
    __shared__ int s[1024];
    int t = threadIdx.x;
    int orig = (t < NTILES) ? g_tile[t] : 0;
    s[t] = orig;
    __syncthreads();
#pragma unroll
    for (int o = 1; o < 1024; o <<= 1) {
        int v = (t >= o) ? s[t - o] : 0;
        __syncthreads();
        s[t] += v;
        __syncthreads();
    }
    if (t < NTILES) g_tile[t] = s[t] - orig;
}

__global__ __launch_bounds__(256) void scan3_kernel()
{
    int add = g_tile[blockIdx.x];
    int base = blockIdx.x * 1024 + threadIdx.x * 4;
#pragma unroll
    for (int j = 0; j < 4; ++j)
        if (base + j < SCAN_N) g_off[base + j] += add;
    if (blockIdx.x == 0 && threadIdx.x == 0) g_off[SCAN_N] = TOT_E;
}

// ---------------- CSR fill ----------------
__global__ void fill_kernel(const int* __restrict__ rows, const int* __restrict__ cols,
                            const float* __restrict__ vals)
{
    int idx = blockIdx.x * blockDim.x + threadIdx.x;
    if (idx >= NUM_R * N_EDGES) return;
    int r = idx / N_EDGES;
    int row = rows[idx], col = cols[idx];
    int vb = __float_as_int(vals[idx]);
    int kR = r * N_USERS + row;
    int pR = g_off[kR] + atomicAdd(&g_cur[kR], 1);
    g_csr[pR] = make_int2(col, vb);
    int kC = NUM_R * N_USERS + r * N_ITEMS + col;
    int pC = g_off[kC] + atomicAdd(&g_cur[kC], 1);
    g_csr[pC] = make_int2(row, vb);
}

// ---------------- CSR SpMM: warp per dst row (R7, unchanged) ----------------
__global__ __launch_bounds__(256) void spmm_csr_kernel(const float* __restrict__ feats,
                                                       int kbase)
{
    int gw = (blockIdx.x * blockDim.x + threadIdx.x) >> 5;
    int lane = threadIdx.x & 31;
    if (gw >= N_USERS) return;
    int e0 = g_off[kbase + gw];
    int e1 = g_off[kbase + gw + 1];
    float4 acc0 = make_float4(0.f, 0.f, 0.f, 0.f);
    float4 acc1 = make_float4(0.f, 0.f, 0.f, 0.f);
    int e = e0;
    for (; e + 1 < e1; e += 2) {
        int2 p0 = __ldg(&g_csr[e]);
        int2 p1 = __ldg(&g_csr[e + 1]);
        float v0 = __int_as_float(p0.y), v1 = __int_as_float(p1.y);
        float4 x0 = __ldg(&reinterpret_cast<const float4*>(feats + (size_t)p0.x * DIM)[lane]);
        float4 x1 = __ldg(&reinterpret_cast<const float4*>(feats + (size_t)p1.x * DIM)[lane]);
        acc0.x = fmaf(v0, x0.x, acc0.x); acc0.y = fmaf(v0, x0.y, acc0.y);
        acc0.z = fmaf(v0, x0.z, acc0.z); acc0.w = fmaf(v0, x0.w, acc0.w);
        acc1.x = fmaf(v1, x1.x, acc1.x); acc1.y = fmaf(v1, x1.y, acc1.y);
        acc1.z = fmaf(v1, x1.z, acc1.z); acc1.w = fmaf(v1, x1.w, acc1.w);
    }
    if (e < e1) {
        int2 p = __ldg(&g_csr[e]);
        float v = __int_as_float(p.y);
        float4 x = __ldg(&reinterpret_cast<const float4*>(feats + (size_t)p.x * DIM)[lane]);
        acc0.x = fmaf(v, x.x, acc0.x); acc0.y = fmaf(v, x.y, acc0.y);
        acc0.z = fmaf(v, x.z, acc0.z); acc0.w = fmaf(v, x.w, acc0.w);
    }
    acc0.x += acc1.x; acc0.y += acc1.y; acc0.z += acc1.z; acc0.w += acc1.w;
    reinterpret_cast<float4*>(g_AGG + (size_t)gw * DIM)[lane] = acc0;
}

// ---------------- weight prep ----------------
__global__ __launch_bounds__(256) void wprep_kernel(const float* __restrict__ Wp,
                                                    const float* __restrict__ Ws)
{
    int w = blockIdx.x;
    const float* W = (w == 0) ? Wp : Ws + (size_t)(w - 1) * DIM * DIM;
    __nv_bfloat16* hi = g_Wb + (size_t)w * 2 * 16384;
    __nv_bfloat16* lo = hi + 16384;
    for (int e = threadIdx.x; e < DIM * DIM; e += blockDim.x) {
        int k = e >> 7, n = e & 127;
        float x = W[e];
        __nv_bfloat16 h = __float2bfloat16(x);
        __nv_bfloat16 l = __float2bfloat16(x - __bfloat162float(h));
        hi[n * DIM + k] = h;
        lo[n * DIM + k] = l;
    }
}

// ================= persistent WMMA update GEMM, 16 warps =================
#define LDA       136
#define ASTRIDE_B (LDA * 2)
#define SM_INV    0
#define SM_STAGE  1024
#define SM_AH     (SM_STAGE + 32768)          // 33792
#define SM_AL     (SM_AH + TM * ASTRIDE_B)    // 51200
#define SM_B      (SM_AL + TM * ASTRIDE_B)    // 68608
#define BMAT      (128 * ASTRIDE_B)           // 34816
#define SM_BYTES  (SM_B + 4 * BMAT)           // 207872

typedef wmma::fragment<wmma::matrix_a, 16, 16, 16, __nv_bfloat16, wmma::row_major> FragA;
typedef wmma::fragment<wmma::matrix_b, 16, 16, 16, __nv_bfloat16, wmma::col_major> FragB;
typedef wmma::fragment<wmma::accumulator, 16, 16, 16, float> FragC;

__device__ __forceinline__ uint32_t smem_u32(const void* p) {
    uint32_t a;
    asm("{ .reg .u64 t; cvta.to.shared.u64 t, %1; cvt.u32.u64 %0, t; }" : "=r"(a) : "l"(p));
    return a;
}
__device__ __forceinline__ void cp_async16(uint32_t smem_dst, const void* gsrc) {
    asm volatile("cp.async.cg.shared.global [%0], [%1], 16;" :: "r"(smem_dst), "l"(gsrc));
}
#define CP_COMMIT() asm volatile("cp.async.commit_group;" ::: "memory")
#define CP_WAIT0()  asm volatile("cp.async.wait_group 0;" ::: "memory")

__device__ __forceinline__ void stage_load(const float* __restrict__ src, int bm, int M,
                                           uint32_t stageAddr, int tid)
{
#pragma unroll
    for (int i = 0; i < 4; ++i) {
        int idx = i * NTH + tid;            // 2048 16B chunks
        int r = idx >> 5, c4 = idx & 31;
        int rowg = bm + r;
        if (rowg >= M) rowg = M - 1;
        cp_async16(stageAddr + (uint32_t)idx * 16, src + (size_t)rowg * DIM + c4 * 4);
    }
    CP_COMMIT();
}

__device__ __forceinline__ void cvt_stage(const char* __restrict__ stage, char* hi, char* lo,
                                          const float* sInv, int tid, bool scale)
{
#pragma unroll
    for (int it = 0; it < 4; ++it) {
        int idx = it * NTH + tid;
        int r = idx >> 5, c4 = idx & 31;
        float4 v = *reinterpret_cast<const float4*>(stage + (size_t)idx * 16);
        if (scale) { float s = sInv[r]; v.x *= s; v.y *= s; v.z *= s; v.w *= s; }
        __nv_bfloat162 h01 = __floats2bfloat162_rn(v.x, v.y);
        __nv_bfloat162 h23 = __floats2bfloat162_rn(v.z, v.w);
        __nv_bfloat162 l01 = __floats2bfloat162_rn(v.x - __bfloat162float(h01.x),
                                                   v.y - __bfloat162float(h01.y));
        __nv_bfloat162 l23 = __floats2bfloat162_rn(v.z - __bfloat162float(h23.x),
                                                   v.w - __bfloat162float(h23.y));
        uint32_t off = (uint32_t)r * ASTRIDE_B + (uint32_t)c4 * 8;
        uint2 hv, lv;
        memcpy(&hv.x, &h01, 4); memcpy(&hv.y, &h23, 4);
        memcpy(&lv.x, &l01, 4); memcpy(&lv.y, &l23, 4);
        *reinterpret_cast<uint2*>(hi + off) = hv;
        *reinterpret_cast<uint2*>(lo + off) = lv;
    }
}

// fused split-GEMM phase: acc += AH·(BH+BL)^T + AL·BH^T, sharing fragment loads
__device__ __forceinline__ void mma_phase(const __nv_bfloat16* aHs, const __nv_bfloat16* aLs,
                                          const __nv_bfloat16* bHs, const __nv_bfloat16* bLs,
                                          FragC (&acc)[2])
{
#pragma unroll
    for (int ks = 0; ks < 8; ++ks) {
        FragA fah, fal;
        FragB fbh[2], fbl[2];
        wmma::load_matrix_sync(fah, aHs + ks * 16, LDA);
        wmma::load_matrix_sync(fal, aLs + ks * 16, LDA);
        wmma::load_matrix_sync(fbh[0], bHs + ks * 16, LDA);
        wmma::load_matrix_sync(fbh[1], bHs + (size_t)16 * LDA + ks * 16, LDA);
        wmma::load_matrix_sync(fbl[0], bLs + ks * 16, LDA);
        wmma::load_matrix_sync(fbl[1], bLs + (size_t)16 * LDA + ks * 16, LDA);
#pragma unroll
        for (int j = 0; j < 2; ++j) {
            wmma::mma_sync(acc[j], fah, fbh[j], acc[j]);
            wmma::mma_sync(acc[j], fah, fbl[j], acc[j]);
            wmma::mma_sync(acc[j], fal, fbh[j], acc[j]);
        }
    }
}

__global__ __launch_bounds__(NTH, 1)
void update_mma_kernel(float* __restrict__ X, const float* __restrict__ deg,
                       const __nv_bfloat16* __restrict__ wp_pair,
                       const __nv_bfloat16* __restrict__ ws_pair, int M)
{
    extern __shared__ char sm[];
    const uint32_t sb = smem_u32(sm);
    const int tid = threadIdx.x;
    const int wid = tid >> 5;
    const int mg  = wid & 3;    // m16 group (4 x 16 = 64)
    const int ng  = wid >> 2;   // n32 group (4 x 32 = 128)

    // ---- load all 4 B matrices to smem once ----
    {
        const float4* srcs[4] = {
            reinterpret_cast<const float4*>(wp_pair),
            reinterpret_cast<const float4*>(wp_pair + 16384),
            reinterpret_cast<const float4*>(ws_pair),
            reinterpret_cast<const float4*>(ws_pair + 16384)};
#pragma unroll
        for (int w = 0; w < 4; ++w) {
            char* dst = sm + SM_B + w * BMAT;
#pragma unroll
            for (int i = 0; i < 4; ++i) {
                int idx = i * NTH + tid;            // 2048 float4
                int row = idx >> 4, c = idx & 15;
                *reinterpret_cast<float4*>(dst + (uint32_t)row * ASTRIDE_B + c * 16) = srcs[w][idx];
            }
        }
    }

    float* sInv = (float*)(sm + SM_INV);
    const uint32_t stageAddr = sb + SM_STAGE;
    char* stage = sm + SM_STAGE;
    char* aHbuf = sm + SM_AH;
    char* aLbuf = sm + SM_AL;

    const __nv_bfloat16* aHs = (const __nv_bfloat16*)aHbuf + (size_t)mg * 16 * LDA;
    const __nv_bfloat16* aLs = (const __nv_bfloat16*)aLbuf + (size_t)mg * 16 * LDA;
    const __nv_bfloat16* bPH = (const __nv_bfloat16*)(sm + SM_B + 0 * BMAT) + (size_t)ng * 32 * LDA;
    const __nv_bfloat16* bPL = (const __nv_bfloat16*)(sm + SM_B + 1 * BMAT) + (size_t)ng * 32 * LDA;
    const __nv_bfloat16* bSH = (const __nv_bfloat16*)(sm + SM_B + 2 * BMAT) + (size_t)ng * 32 * LDA;
    const __nv_bfloat16* bSL = (const __nv_bfloat16*)(sm + SM_B + 3 * BMAT) + (size_t)ng * 32 * LDA;

    stage_load(X, (int)blockIdx.x * TM, M, stageAddr, tid);

    for (int t = blockIdx.x; t < NT; t += GRID_U) {
        const int bm = t * TM;
        if (tid < TM) {
            int rowg = bm + tid;
            sInv[tid] = (rowg < M) ? 1.0f / (deg[rowg] + 1.0f) : 0.0f;
        }

        FragC acc[2];
#pragma unroll
        for (int j = 0; j < 2; ++j) wmma::fill_fragment(acc[j], 0.0f);

        // ===== phase 0: A = X, B = Wp =====
        CP_WAIT0();
        __syncthreads();
        cvt_stage(stage, aHbuf, aLbuf, sInv, tid, false);
        __syncthreads();
        stage_load(g_AGG, bm, M, stageAddr, tid);   // prefetch AGG during MMA
        mma_phase(aHs, aLs, bPH, bPL, acc);

        // ===== phase 1: A = inv*AGG, B = Ws =====
        CP_WAIT0();
        __syncthreads();
        cvt_stage(stage, aHbuf, aLbuf, sInv, tid, true);
        __syncthreads();
        if (t + GRID_U < NT)
            stage_load(X, (t + GRID_U) * TM, M, stageAddr, tid);
        mma_phase(aHs, aLs, bSH, bSL, acc);

        // ===== epilogue: direct global store (whole-fragment rows; M % 16 == 0) =====
#pragma unroll
        for (int j = 0; j < 2; ++j) {
            int row0 = bm + mg * 16;
            if (row0 < M)
                wmma::store_matrix_sync(X + (size_t)row0 * DIM + ng * 32 + j * 16,
                                        acc[j], DIM, wmma::mem_row_major);
        }
    }
}

// ---------------- final leaky-relu + write out [U ; I] ----------------
__global__ void finalize_kernel(float* __restrict__ out)
{
    const size_t half4  = (size_t)N_USERS * DIM / 4;
    const size_t total4 = 2 * half4;
    size_t idx = (size_t)blockIdx.x * blockDim.x + threadIdx.x;
    if (idx >= total4) return;
    float4 v = (idx < half4) ? reinterpret_cast<const float4*>(g_U)[idx]
                             : reinterpret_cast<const float4*>(g_I)[idx - half4];
    v.x = v.x > 0.f ? v.x : 0.01f * v.x;
    v.y = v.y > 0.f ? v.y : 0.01f * v.y;
    v.z = v.z > 0.f ? v.z : 0.01f * v.z;
    v.w = v.w > 0.f ? v.w : 0.01f * v.w;
    reinterpret_cast<float4*>(out)[idx] = v;
}

// ---------------- launch ----------------
extern "C" void kernel_launch(void* const* d_in, const int* in_sizes, int n_in,
                              void* d_out, int out_size)
{
    const float* u_emb = (const float*)d_in[0];
    const float* i_emb = (const float*)d_in[1];
    const float* Wp    = (const float*)d_in[2];
    const float* Ws    = (const float*)d_in[3];
    const float* vals  = (const float*)d_in[4];
    const int*   rows  = (const int*)d_in[5];
    const int*   cols  = (const int*)d_in[6];
    float*       out   = (float*)d_out;

    void *pU, *pI, *pDU, *pDI, *pWb, *pCnt, *pCur;
    cudaGetSymbolAddress(&pU,  g_U);
    cudaGetSymbolAddress(&pI,  g_I);
    cudaGetSymbolAddress(&pDU, g_degU);
    cudaGetSymbolAddress(&pDI, g_degI);
    cudaGetSymbolAddress(&pWb, g_Wb);
    cudaGetSymbolAddress(&pCnt, g_cnt);
    cudaGetSymbolAddress(&pCur, g_cur);

    cudaFuncSetAttribute(update_mma_kernel, cudaFuncAttributeMaxDynamicSharedMemorySize, SM_BYTES);

    const size_t embBytes = (size_t)N_USERS * DIM * sizeof(float);
    cudaMemcpyAsync(pU, u_emb, embBytes, cudaMemcpyDeviceToDevice, 0);
    cudaMemcpyAsync(pI, i_emb, embBytes, cudaMemcpyDeviceToDevice, 0);
    cudaMemsetAsync(pDU, 0, sizeof(float) * NUM_R * N_USERS, 0);
    cudaMemsetAsync(pDI, 0, sizeof(float) * NUM_R * N_ITEMS, 0);
    cudaMemsetAsync(pCnt, 0, sizeof(int) * SCAN_N, 0);
    cudaMemsetAsync(pCur, 0, sizeof(int) * SCAN_N, 0);

    wprep_kernel<<<5, 256>>>(Wp, Ws);
    count_kernel<<<(NUM_R * N_EDGES + 255) / 256, 256>>>(rows, cols, vals);
    scan1_kernel<<<NTILES, 256>>>();
    scan2_kernel<<<1, 1024>>>();
    scan3_kernel<<<NTILES, 256>>>();
    fill_kernel<<<(NUM_R * N_EDGES + 255) / 256, 256>>>(rows, cols, vals);

    const int spmm_blocks = (N_USERS * 32 + 255) / 256;
    const __nv_bfloat16* wb = (const __nv_bfloat16*)pWb;

    for (int r = 0; r < NUM_R; ++r) {
        const __nv_bfloat16* wp_pair = wb;
        const __nv_bfloat16* ws_pair = wb + (size_t)(1 + r) * 2 * 16384;

        // ---- u update ----
        spmm_csr_kernel<<<spmm_blocks, 256>>>((const float*)pI, r * N_USERS);
        update_mma_kernel<<<GRID_U, NTH, SM_BYTES>>>(
            (float*)pU, (const float*)pDU + (size_t)r * N_USERS, wp_pair, ws_pair, N_USERS);

        // ---- i update (uses updated U) ----
        spmm_csr_kernel<<<spmm_blocks, 256>>>((const float*)pU, (NUM_R + r) * N_ITEMS);
        update_mma_kernel<<<GRID_U, NTH, SM_BYTES>>>(
            (float*)pI, (const float*)pDI + (size_t)r * N_ITEMS, wp_pair, ws_pair, N_ITEMS);
    }

    const size_t total4 = 2 * ((size_t)N_USERS * DIM / 4);
    finalize_kernel<<<(unsigned)((total4 + 255) / 256), 256>>>(out);
}